// round 1
// baseline (speedup 1.0000x reference)
#include <cuda_runtime.h>
#include <math.h>

#define NSAMP   1048576
#define DDIM    128
#define NCLASS  100
#define CPAD    128     // classes padded to 128 (cols >= 100 masked in epilogue)
#define BM      128     // samples per CTA

// -------- device scratch (no allocations allowed) --------
__device__ double g_acc;
__device__ int    g_present[CPAD];
__device__ int    g_y_is_64;

// -------- init: zero scratch + detect y dtype (int64 vs int32) --------
// If y is int64 (little-endian, values 0..99), every odd 32-bit word of the
// first 128 elements is 0. If y is int32, P(all 128 of those words == 0) ~ 1e-256.
__global__ void init_kernel(const int* __restrict__ y32) {
    int t = threadIdx.x;
    if (t == 0) g_acc = 0.0;
    if (t < CPAD) g_present[t] = 0;
    __shared__ int any_nonzero;
    if (t == 0) any_nonzero = 0;
    __syncthreads();
    if (t < 128) {
        if (y32[2 * t + 1] != 0) atomicOr(&any_nonzero, 1);
    }
    __syncthreads();
    if (t == 0) g_y_is_64 = any_nonzero ? 0 : 1;
}

// -------- main: GEMM tile (128x128x128) + fused log-softmax CE --------
extern __shared__ float smem[];

__global__ __launch_bounds__(256, 1)
void ce_kernel(const float* __restrict__ x,
               const float* __restrict__ anchors,
               const void*  __restrict__ yptr) {
    float* xs = smem;                 // [BM][DDIM]  row-major x tile (64 KB)
    float* as = smem + BM * DDIM;     // [DDIM][CPAD] K-major anchors (64 KB)

    const int tid    = threadIdx.x;
    const int block0 = blockIdx.x * BM;

    // ---- load x tile: one warp per row, coalesced float4 ----
    {
        const int warp = tid >> 5, lane = tid & 31;
        for (int r = warp; r < BM; r += 8) {
            float4 v = ((const float4*)(x + (size_t)(block0 + r) * DDIM))[lane];
            ((float4*)(xs + r * DDIM))[lane] = v;
        }
    }
    // ---- load anchors transposed into as[k][c]; pad classes 100..127 = 0 ----
    {
        const int c  = tid & 127;
        const int kq = tid >> 7;          // 0..1
        for (int k4 = kq; k4 < DDIM / 4; k4 += 2) {
            float4 v = make_float4(0.f, 0.f, 0.f, 0.f);
            if (c < NCLASS) v = ((const float4*)(anchors + c * DDIM))[k4];
            as[(k4 * 4 + 0) * CPAD + c] = v.x;
            as[(k4 * 4 + 1) * CPAD + c] = v.y;
            as[(k4 * 4 + 2) * CPAD + c] = v.z;
            as[(k4 * 4 + 3) * CPAD + c] = v.w;
        }
    }
    __syncthreads();

    // ---- register-tiled GEMM: thread = 8 rows x 8 cols ----
    const int tx = tid & 15;          // class group  (16 groups of 8)
    const int ty = tid >> 4;          // sample group (16 groups of 8)

    float acc[8][8];
#pragma unroll
    for (int j = 0; j < 8; j++)
#pragma unroll
        for (int i = 0; i < 8; i++) acc[j][i] = 0.f;

    const float* xbase = xs + (ty * 8) * DDIM;
    const float* abase = as + tx * 8;

#pragma unroll 4
    for (int k = 0; k < DDIM; k += 4) {
        float xr[8][4];
#pragma unroll
        for (int j = 0; j < 8; j++) {
            float4 v = *(const float4*)(xbase + j * DDIM + k);
            xr[j][0] = v.x; xr[j][1] = v.y; xr[j][2] = v.z; xr[j][3] = v.w;
        }
        float ar[4][8];
#pragma unroll
        for (int kk = 0; kk < 4; kk++) {
            float4 a0 = *(const float4*)(abase + (k + kk) * CPAD);
            float4 a1 = *(const float4*)(abase + (k + kk) * CPAD + 4);
            ar[kk][0] = a0.x; ar[kk][1] = a0.y; ar[kk][2] = a0.z; ar[kk][3] = a0.w;
            ar[kk][4] = a1.x; ar[kk][5] = a1.y; ar[kk][6] = a1.z; ar[kk][7] = a1.w;
        }
#pragma unroll
        for (int kk = 0; kk < 4; kk++)
#pragma unroll
            for (int j = 0; j < 8; j++)
#pragma unroll
                for (int i = 0; i < 8; i++)
                    acc[j][i] = fmaf(xr[j][kk], ar[kk][i], acc[j][i]);
    }

    // ---- stage scores into smem (reuse xs region): sc[m][c] ----
    __syncthreads();
    float* sc = xs;                   // [BM][CPAD] = 64 KB, aliases x tile
#pragma unroll
    for (int j = 0; j < 8; j++) {
        int row = ty * 8 + j;
        *(float4*)(sc + row * CPAD + tx * 8)     =
            make_float4(acc[j][0], acc[j][1], acc[j][2], acc[j][3]);
        *(float4*)(sc + row * CPAD + tx * 8 + 4) =
            make_float4(acc[j][4], acc[j][5], acc[j][6], acc[j][7]);
    }
    __syncthreads();

    // ---- epilogue: warp per row, masked logsumexp + CE ----
    const int warp = tid >> 5, lane = tid & 31;
    const long long* y64 = (const long long*)yptr;
    const int*       y32 = (const int*)yptr;
    const int is64 = g_y_is_64;

    float wsum = 0.f;
    for (int rr = 0; rr < 16; rr++) {
        const int row = warp * 16 + rr;
        float v[4];
#pragma unroll
        for (int j = 0; j < 4; j++) {
            int col = lane + 32 * j;
            float s = sc[row * CPAD + col];
            v[j] = (col < NCLASS) ? s : -1e30f;
        }
        float mx = fmaxf(fmaxf(v[0], v[1]), fmaxf(v[2], v[3]));
#pragma unroll
        for (int o = 16; o > 0; o >>= 1)
            mx = fmaxf(mx, __shfl_xor_sync(0xffffffffu, mx, o));
        float se = 0.f;
#pragma unroll
        for (int j = 0; j < 4; j++)
            se += (lane + 32 * j < NCLASS) ? expf(v[j] - mx) : 0.f;
#pragma unroll
        for (int o = 16; o > 0; o >>= 1)
            se += __shfl_xor_sync(0xffffffffu, se, o);

        int yv = 0;
        if (lane == 0) {
            long long g = block0 + row;
            yv = is64 ? (int)y64[g] : y32[g];
        }
        yv = __shfl_sync(0xffffffffu, yv, 0);
        float sy = sc[row * CPAD + yv];   // broadcast read

        if (lane == 0) {
            wsum += (logf(se) + mx) - sy;
            g_present[yv] = 1;            // racy writes of '1' are fine
        }
    }
    if (lane == 0) atomicAdd(&g_acc, (double)wsum);
}

// -------- finalize: n_present & scalar output --------
__global__ void final_kernel(float* __restrict__ out) {
    __shared__ int cnt;
    if (threadIdx.x == 0) cnt = 0;
    __syncthreads();
    if (threadIdx.x < NCLASS && g_present[threadIdx.x]) atomicAdd(&cnt, 1);
    __syncthreads();
    if (threadIdx.x == 0)
        out[0] = (float)(g_acc * ((double)cnt / (double)NSAMP));
}

// -------- launch --------
extern "C" void kernel_launch(void* const* d_in, const int* in_sizes, int n_in,
                              void* d_out, int out_size) {
    // Identify inputs by element count (robust to metadata ordering):
    const float* x = nullptr; const float* anchors = nullptr; const void* y = nullptr;
    for (int i = 0; i < n_in; i++) {
        if (in_sizes[i] == NSAMP * DDIM)      x       = (const float*)d_in[i];
        else if (in_sizes[i] == NCLASS * DDIM) anchors = (const float*)d_in[i];
        else if (in_sizes[i] == NSAMP)         y       = d_in[i];
    }
    float* out = (float*)d_out;

    const size_t smem_bytes = (size_t)(BM * DDIM + DDIM * CPAD) * sizeof(float); // 128 KB
    cudaFuncSetAttribute(ce_kernel, cudaFuncAttributeMaxDynamicSharedMemorySize,
                         (int)smem_bytes);

    init_kernel<<<1, 256>>>((const int*)y);
    ce_kernel<<<NSAMP / BM, 256, smem_bytes>>>(x, anchors, y);
    final_kernel<<<1, 128>>>(out);
}

// round 4
// speedup vs baseline: 7.5839x; 7.5839x over previous
#include <cuda_runtime.h>
#include <cuda_bf16.h>
#include <cstdint>
#include <math.h>

#define NSAMP   1048576
#define DDIM    128
#define NCLASS  100
#define BM      128
#define NTILES  (NSAMP / BM)     // 8192
#define THREADS 512
#define LDSB    272              // smem row stride in bytes (136 bf16)

// ---- smem layout (bytes) ----
#define SM_ANCH   0              // [128][136] bf16 = 34816
#define SM_X0     34816          // [128][136] bf16
#define SM_X1     69632
#define SM_REDMAX 104448         // 4*128 floats
#define SM_REDSUM 106496
#define SM_REDSY  108544
#define SM_YS     110592         // 128 ints
#define SM_TOTAL  111104

// ---- device scratch ----
__device__ double       g_acc;
__device__ unsigned int g_present[4];
__device__ int          g_y_is_64;

// ---- helpers ----
__device__ __forceinline__ uint32_t smem_u32(const void* p) {
    uint32_t a;
    asm("{ .reg .u64 t; cvta.to.shared.u64 t, %1; cvt.u32.u64 %0, t; }" : "=r"(a) : "l"(p));
    return a;
}

__device__ __forceinline__ void ldmatrix_x4(uint32_t* r, uint32_t addr) {
    asm volatile("ldmatrix.sync.aligned.m8n8.x4.shared.b16 {%0,%1,%2,%3}, [%4];"
                 : "=r"(r[0]), "=r"(r[1]), "=r"(r[2]), "=r"(r[3]) : "r"(addr));
}
__device__ __forceinline__ void ldmatrix_x2(uint32_t* r, uint32_t addr) {
    asm volatile("ldmatrix.sync.aligned.m8n8.x2.shared.b16 {%0,%1}, [%2];"
                 : "=r"(r[0]), "=r"(r[1]) : "r"(addr));
}
__device__ __forceinline__ void mma_bf16(float* c, const uint32_t* a, const uint32_t* b) {
    asm volatile("mma.sync.aligned.m16n8k16.row.col.f32.bf16.bf16.f32 "
                 "{%0,%1,%2,%3}, {%4,%5,%6,%7}, {%8,%9}, {%0,%1,%2,%3};"
                 : "+f"(c[0]), "+f"(c[1]), "+f"(c[2]), "+f"(c[3])
                 : "r"(a[0]), "r"(a[1]), "r"(a[2]), "r"(a[3]), "r"(b[0]), "r"(b[1]));
}

__device__ __forceinline__ uint2 f4_to_bf16x4(float4 v) {
    __nv_bfloat162 lo = __float22bfloat162_rn(make_float2(v.x, v.y));
    __nv_bfloat162 hi = __float22bfloat162_rn(make_float2(v.z, v.w));
    uint2 r;
    r.x = *reinterpret_cast<uint32_t*>(&lo);
    r.y = *reinterpret_cast<uint32_t*>(&hi);
    return r;
}

// ---- init: zero scratch + y dtype sniff (int64 vs int32) ----
__global__ void init_kernel(const int* __restrict__ y32) {
    int t = threadIdx.x;
    if (t == 0) g_acc = 0.0;
    if (t < 4) g_present[t] = 0u;
    __shared__ int any_nz;
    if (t == 0) any_nz = 0;
    __syncthreads();
    if (t < 128 && y32[2 * t + 1] != 0) atomicOr(&any_nz, 1);
    __syncthreads();
    if (t == 0) g_y_is_64 = any_nz ? 0 : 1;
}

// ---- main persistent fused kernel ----
extern __shared__ char smem[];

__global__ __launch_bounds__(THREADS, 1)
void ce_mma_kernel(const float* __restrict__ x,
                   const float* __restrict__ anchors,
                   const void*  __restrict__ yptr) {
    const uint32_t sbase = smem_u32(smem);
    const int tid  = threadIdx.x;
    const int wid  = tid >> 5;
    const int lane = tid & 31;
    const int wm   = wid & 3;            // row block (32 rows)
    const int wn   = wid >> 2;           // col block (32 cols)
    const int bid  = blockIdx.x;
    const int G    = gridDim.x;

    const int is64 = g_y_is_64;
    const long long* y64 = (const long long*)yptr;
    const int*       y32 = (const int*)yptr;

    float* redmax = (float*)(smem + SM_REDMAX);
    float* redsum = (float*)(smem + SM_REDSUM);
    float* redsy  = (float*)(smem + SM_REDSY);
    int*   ys     = (int*)  (smem + SM_YS);

    // ---- prologue: anchors fp32 -> bf16 smem [row][136], zero-pad rows 100..127 ----
    for (int i = tid; i < NCLASS * 32; i += THREADS) {
        int row = i >> 5, c4 = i & 31;
        float4 v = ((const float4*)anchors)[i];
        *(uint2*)(smem + SM_ANCH + row * LDSB + c4 * 8) = f4_to_bf16x4(v);
    }
    for (int i = tid; i < (128 - NCLASS) * 32; i += THREADS) {
        int row = NCLASS + (i >> 5), c4 = i & 31;
        *(uint2*)(smem + SM_ANCH + row * LDSB + c4 * 8) = make_uint2(0u, 0u);
    }
    // first x tile -> buf0
    {
        const float4* src = (const float4*)(x + (size_t)bid * BM * DDIM);
#pragma unroll
        for (int t = 0; t < 8; t++) {
            int i = tid + t * THREADS;
            int row = i >> 5, c4 = i & 31;
            *(uint2*)(smem + SM_X0 + row * LDSB + c4 * 8) = f4_to_bf16x4(src[i]);
        }
    }
    __syncthreads();

    const int S = (NTILES - bid + G - 1) / G;

    float        ce_acc = 0.f;
    unsigned int pm[4]  = {0u, 0u, 0u, 0u};

    // ldmatrix base addresses (per-warp/lane constants; add buf offset + ks*32)
    const uint32_t a_row_off = (uint32_t)((wm * 32 + (lane & 15)) * LDSB + (lane >> 4) * 16);
    const uint32_t b_addr0   = sbase + SM_ANCH +
                               (uint32_t)((wn * 32 + (lane & 7)) * LDSB + ((lane >> 3) & 1) * 16);
    const uint32_t xoff[2] = {SM_X0, SM_X1};

    for (int s = 0; s < S; s++) {
        const int tile = bid + s * G;

        // 1) prefetch next tile into registers (deep MLP, consumed at iter end)
        float4 pf[8];
        const bool havenext = (s + 1 < S);
        if (havenext) {
            const float4* src = (const float4*)(x + (size_t)(bid + (s + 1) * G) * BM * DDIM);
#pragma unroll
            for (int t = 0; t < 8; t++) pf[t] = src[tid + t * THREADS];
        }

        // 2) mma over K=128 from smem buf[s&1]
        float acc[2][4][4];
#pragma unroll
        for (int mt = 0; mt < 2; mt++)
#pragma unroll
            for (int nt = 0; nt < 4; nt++)
#pragma unroll
                for (int j = 0; j < 4; j++) acc[mt][nt][j] = 0.f;

        const uint32_t abase = sbase + xoff[s & 1] + a_row_off;
#pragma unroll
        for (int ks = 0; ks < 8; ks++) {
            uint32_t afrag[2][4];
            ldmatrix_x4(afrag[0], abase + ks * 32);
            ldmatrix_x4(afrag[1], abase + ks * 32 + 16 * LDSB);
            uint32_t bfrag[4][2];
#pragma unroll
            for (int nt = 0; nt < 4; nt++)
                ldmatrix_x2(bfrag[nt], b_addr0 + nt * 8 * LDSB + ks * 32);
#pragma unroll
            for (int mt = 0; mt < 2; mt++)
#pragma unroll
                for (int nt = 0; nt < 4; nt++)
                    mma_bf16(acc[mt][nt], afrag[mt], bfrag[nt]);
        }

        // 3) load y tile into smem
        if (tid < BM) {
            long long grow = (long long)tile * BM + tid;
            ys[tid] = is64 ? (int)y64[grow] : y32[grow];
        }
        __syncthreads();

        // 4) per-row partial logsumexp over this warp's 32-col chunk
#pragma unroll
        for (int mt = 0; mt < 2; mt++) {
#pragma unroll
            for (int h = 0; h < 2; h++) {
                const int row = wm * 32 + mt * 16 + h * 8 + (lane >> 2);
                const int yv  = ys[row];
                float v[8];
                float mx = -1e30f;
#pragma unroll
                for (int nt = 0; nt < 4; nt++) {
#pragma unroll
                    for (int j = 0; j < 2; j++) {
                        int col = wn * 32 + nt * 8 + 2 * (lane & 3) + j;
                        float val = acc[mt][nt][h * 2 + j];
                        val = (col < NCLASS) ? val : -1e30f;
                        v[nt * 2 + j] = val;
                        mx = fmaxf(mx, val);
                    }
                }
                mx = fmaxf(mx, __shfl_xor_sync(0xffffffffu, mx, 1));
                mx = fmaxf(mx, __shfl_xor_sync(0xffffffffu, mx, 2));
                float se = 0.f, sy = 0.f;
#pragma unroll
                for (int nt = 0; nt < 4; nt++) {
#pragma unroll
                    for (int j = 0; j < 2; j++) {
                        int col = wn * 32 + nt * 8 + 2 * (lane & 3) + j;
                        float val = v[nt * 2 + j];
                        se += __expf(val - mx);
                        if (col == yv) sy = val;
                    }
                }
                se += __shfl_xor_sync(0xffffffffu, se, 1);
                se += __shfl_xor_sync(0xffffffffu, se, 2);
                sy += __shfl_xor_sync(0xffffffffu, sy, 1);
                sy += __shfl_xor_sync(0xffffffffu, sy, 2);
                if ((lane & 3) == 0) {
                    redmax[wn * 128 + row] = mx;
                    redsum[wn * 128 + row] = se;
                    redsy [wn * 128 + row] = sy;
                }
            }
        }
        __syncthreads();

        // 5) final per-row combine (threads 0..127)
        if (tid < BM) {
            const int r = tid;
            float m0 = redmax[r],       s0 = redsum[r];
            float m1 = redmax[128 + r], s1 = redsum[128 + r];
            float m2 = redmax[256 + r], s2 = redsum[256 + r];
            float m3 = redmax[384 + r], s3 = redsum[384 + r];
            float M  = fmaxf(fmaxf(m0, m1), fmaxf(m2, m3));
            float Ss = s0 * __expf(m0 - M) + s1 * __expf(m1 - M)
                     + s2 * __expf(m2 - M) + s3 * __expf(m3 - M);
            int yv = ys[r];
            float sy = redsy[(yv >> 5) * 128 + r];
            ce_acc += (__logf(Ss) + M) - sy;
            pm[yv >> 5] |= 1u << (yv & 31);
        }

        // 6) store prefetched tile s+1 into the other buffer
        if (havenext) {
            const uint32_t dst = xoff[(s + 1) & 1];
#pragma unroll
            for (int t = 0; t < 8; t++) {
                int i = tid + t * THREADS;
                int row = i >> 5, c4 = i & 31;
                *(uint2*)(smem + dst + row * LDSB + c4 * 8) = f4_to_bf16x4(pf[t]);
            }
        }
        __syncthreads();
    }

    // ---- CTA reductions ----
#pragma unroll
    for (int o = 16; o > 0; o >>= 1)
        ce_acc += __shfl_xor_sync(0xffffffffu, ce_acc, o);
    if (lane == 0 && wid < 4) atomicAdd(&g_acc, (double)ce_acc);
#pragma unroll
    for (int k = 0; k < 4; k++) {
        unsigned v = __reduce_or_sync(0xffffffffu, pm[k]);
        if (lane == 0 && wid < 4 && v) atomicOr(&g_present[k], v);
    }
}

// ---- finalize ----
__global__ void final_kernel(float* __restrict__ out) {
    if (threadIdx.x == 0) {
        int cnt = 0;
        for (int k = 0; k < 4; k++) cnt += __popc(g_present[k]);
        out[0] = (float)(g_acc * ((double)cnt / (double)NSAMP));
    }
}

// ---- launch ----
extern "C" void kernel_launch(void* const* d_in, const int* in_sizes, int n_in,
                              void* d_out, int out_size) {
    const float* x = nullptr; const float* anchors = nullptr; const void* y = nullptr;
    for (int i = 0; i < n_in; i++) {
        if (in_sizes[i] == NSAMP * DDIM)       x       = (const float*)d_in[i];
        else if (in_sizes[i] == NCLASS * DDIM) anchors = (const float*)d_in[i];
        else if (in_sizes[i] == NSAMP)         y       = d_in[i];
    }
    float* out = (float*)d_out;

    int nsm = 0;
    cudaDeviceGetAttribute(&nsm, cudaDevAttrMultiProcessorCount, 0);
    if (nsm <= 0) nsm = 148;

    cudaFuncSetAttribute(ce_mma_kernel,
                         cudaFuncAttributeMaxDynamicSharedMemorySize, SM_TOTAL);

    init_kernel<<<1, 256>>>((const int*)y);
    ce_mma_kernel<<<nsm, THREADS, SM_TOTAL>>>(x, anchors, y);
    final_kernel<<<1, 32>>>(out);
}